// round 2
// baseline (speedup 1.0000x reference)
#include <cuda_runtime.h>
#include <math.h>

// Problem constants (FrameReducer: N=16, T=2048, C=512, V=500)
#define PN 16
#define PT 2048
#define PC 512
#define PV 500

// Scratch (device globals; no allocation allowed)
__device__ int g_src[PN * PT];   // g_src[n*PT + r] = source frame index t for rank r
__device__ int g_lens[PN];       // lens_fr per batch row

// threshold: float32(log(0.9)) — matches jnp float32 weak-typed comparison
#define LOG09 (-0.10536051565782628f)

// ---------------------------------------------------------------------------
// Robust x_lens read: JAX with x64 disabled dumps int32 despite astype(int64).
// Detect dtype from the first 64 bytes only (always in-bounds):
//   int64 layout: words[1,3,...,15] are high words of values in [1,2048] -> 0
//   int32 layout: words[1,3,...,15] are lens[1],lens[3],... in [1,2048] -> !=0
// ---------------------------------------------------------------------------
__device__ __forceinline__ long long read_xlen(const void* p, int n) {
    const int* w = (const int*)p;
    bool is64 = true;
#pragma unroll
    for (int i = 1; i < 16; i += 2) {
        if (w[i] != 0) { is64 = false; break; }
    }
    if (is64) return ((const long long*)p)[n];
    return (long long)w[n];
}

// ---------------------------------------------------------------------------
// Kernel 1: per-row mask + stable compaction scan.
// One block per n, 256 threads, 8 consecutive t per thread.
// ---------------------------------------------------------------------------
__global__ void mask_scan_kernel(const float* __restrict__ ctc,
                                 const void* __restrict__ x_lens,
                                 const int* __restrict__ blank_ptr) {
    const int n = blockIdx.x;
    const int tid = threadIdx.x;                 // 0..255
    const int blank = blank_ptr ? blank_ptr[0] : 0;
    const long long xl = read_xlen(x_lens, n);

    bool keep[8];
    int cnt = 0;
#pragma unroll
    for (int i = 0; i < 8; i++) {
        const int t = tid * 8 + i;
        bool k = false;
        if ((long long)t < xl) {
            const float v = ctc[((size_t)n * PT + t) * PV + blank];
            k = (v < LOG09);
        }
        keep[i] = k;
        cnt += k ? 1 : 0;
    }

    __shared__ int s[256];
    s[tid] = cnt;
    __syncthreads();
    // Hillis-Steele inclusive scan over 256 per-thread counts
    for (int off = 1; off < 256; off <<= 1) {
        int v = (tid >= off) ? s[tid - off] : 0;
        __syncthreads();
        s[tid] += v;
        __syncthreads();
    }
    int base = s[tid] - cnt;                     // exclusive prefix for this thread
    if (tid == 255) g_lens[n] = s[255];

#pragma unroll
    for (int i = 0; i < 8; i++) {
        const int t = tid * 8 + i;
        if (keep[i]) {
            g_src[n * PT + base] = t;
            base++;
        }
    }
}

// ---------------------------------------------------------------------------
// Kernel 2: gather/zero-fill. One block per output row (n, r), 128 threads,
// float4 => 128*16B = 2048B = one row of C=512 floats. Every output element
// written exactly once (no memset needed; d_out is poisoned).
// ---------------------------------------------------------------------------
__global__ void gather_kernel(const float* __restrict__ x,
                              float* __restrict__ out,
                              int t_prime) {
    const int r = blockIdx.x % t_prime;
    const int n = blockIdx.x / t_prime;
    const int lane = threadIdx.x;                // 0..127

    float4 val = make_float4(0.f, 0.f, 0.f, 0.f);
    if (r < g_lens[n]) {
        const int t = g_src[n * PT + r];
        val = reinterpret_cast<const float4*>(x + ((size_t)n * PT + t) * PC)[lane];
    }
    reinterpret_cast<float4*>(out + ((size_t)n * t_prime + r) * PC)[lane] = val;
}

// ---------------------------------------------------------------------------
// Kernel 3: optional lens_fr tail (if harness concatenated the second output).
// rem == PN      -> lens cast to float32 (single-dtype output buffer)
// rem == 2*PN    -> lens as int64 occupying 2 float slots each
// ---------------------------------------------------------------------------
__global__ void tail_kernel(float* __restrict__ out, int t_prime, int rem) {
    const int i = threadIdx.x;
    if (i >= PN) return;
    const size_t off = (size_t)PN * t_prime * PC;
    if (rem == PN) {
        out[off + i] = (float)g_lens[i];
    } else if (rem == 2 * PN) {
        reinterpret_cast<long long*>(out + off)[i] = (long long)g_lens[i];
    }
}

// ---------------------------------------------------------------------------
extern "C" void kernel_launch(void* const* d_in, const int* in_sizes, int n_in,
                              void* d_out, int out_size) {
    const float* x      = (const float*)d_in[0];    // [N,T,C] f32
    const void*  x_lens = d_in[1];                  // [N] i32 or i64 (detected)
    const float* ctc    = (const float*)d_in[2];    // [N,T,V] f32
    const int*   blank  = (n_in >= 4) ? (const int*)d_in[3] : nullptr;
    float*       out    = (float*)d_out;

    // T' is fixed by the harness via out_size: out_size = N*T'*C (+ optional lens tail)
    const int row = PN * PC;                 // 8192
    int t_prime = out_size / row;
    int rem = out_size - t_prime * row;
    if (t_prime < 1) t_prime = 1;

    mask_scan_kernel<<<PN, 256>>>(ctc, x_lens, blank);
    gather_kernel<<<PN * t_prime, 128>>>(x, out, t_prime);
    if (rem > 0) {
        tail_kernel<<<1, 32>>>(out, t_prime, rem);
    }
}